// round 15
// baseline (speedup 1.0000x reference)
#include <cuda_runtime.h>
#include <cuda_bf16.h>
#include <mma.h>
#include <math.h>
#include <stdint.h>

#define SEGN 512
#define NLAY 6
#define NSEGS 8
#define FFD 2048
#define FULLN 1536

typedef unsigned long long u64;
using namespace nvcuda;

// ---------------- packed fp32 math (Blackwell FFMA2, PTX-only) ----------------
__device__ __forceinline__ u64 ffma2(u64 a, u64 b, u64 c) {
    u64 d;
    asm("fma.rn.f32x2 %0, %1, %2, %3;" : "=l"(d) : "l"(a), "l"(b), "l"(c));
    return d;
}
__device__ __forceinline__ u64 pack2(float x, float y) {
    u64 d;
    asm("mov.b64 %0, {%1, %2};" : "=l"(d)
        : "r"(__float_as_uint(x)), "r"(__float_as_uint(y)));
    return d;
}
__device__ __forceinline__ float2 unpk(u64 a) {
    unsigned lo, hi;
    asm("mov.b64 {%0, %1}, %2;" : "=r"(lo), "=r"(hi) : "l"(a));
    return make_float2(__uint_as_float(lo), __uint_as_float(hi));
}

// ---------------- fp32 scratch ----------------
__device__ float g_R[FULLN * 512];
__device__ float g_state[2][SEGN * 512];
__device__ float g_Apu[2][SEGN * 512];               // q + u (fp32, FFMA2 A)
__device__ float g_kbuf[2][NLAY][2][FULLN * 512];    // ping-pong k only
__device__ float g_vbuf[2][NLAY][2][FULLN * 512];    // ping-pong v
__device__ float g_scores[2][SEGN * FULLN];
__device__ float g_av[2][SEGN * 512];
__device__ float g_h[2][SEGN * 512];
__device__ float g_ffpart[2][4][SEGN * 512];         // split-K partials (av/wo/w2)

// ---------------- bf16 split scratch (tensor-core path) ----------------
__device__ __nv_bfloat16 g_w1_hi[2][6 * 2048 * 512];   // [j][2048 n][512 k]
__device__ __nv_bfloat16 g_w1_lo[2][6 * 2048 * 512];
__device__ __nv_bfloat16 g_w2_hi[2][6 * 512 * 2048];   // [j][512 n][2048 k]
__device__ __nv_bfloat16 g_w2_lo[2][6 * 512 * 2048];
__device__ __nv_bfloat16 g_pkhi[2][NLAY][FULLN * 512]; // pk splits (static per launch)
__device__ __nv_bfloat16 g_pklo[2][NLAY][FULLN * 512];
__device__ __nv_bfloat16 g_qvhi[2][SEGN * 512], g_qvlo[2][SEGN * 512];  // q+v splits
__device__ __nv_bfloat16 g_hhi[2][SEGN * 512],  g_hlo[2][SEGN * 512];
__device__ __nv_bfloat16 g_midhi[2][SEGN * FFD], g_midlo[2][SEGN * FFD];

__device__ __forceinline__ void split1(float x, __nv_bfloat16* hi, __nv_bfloat16* lo, size_t i) {
    __nv_bfloat16 h = __float2bfloat16_rn(x);
    hi[i] = h;
    lo[i] = __float2bfloat16_rn(x - __bfloat162float(h));
}

// ---------------- R4 FFMA2 GEMM core (BK16, reg prefetch) ----------------
#define GEMM_DECL                                                              \
    __shared__ float As[16][68];                                               \
    __shared__ float Bs[16][68];                                               \
    u64 acc[2][4] = {{0ull,0ull,0ull,0ull},{0ull,0ull,0ull,0ull}};             \
    const int t  = threadIdx.x;                                                \
    const int tx = t & 15, ty = t >> 4;                                        \
    const int ar = t >> 2, ac = (t & 3) << 2;                                  \
    const int br = t >> 4, bc = (t & 15) << 2;                                 \
    const int row0 = blockIdx.y << 6, col0 = blockIdx.x << 6;                  \
    (void)br; (void)bc; (void)row0; (void)col0;

#define INNER16                                                                \
    _Pragma("unroll")                                                          \
    for (int kk = 0; kk < 16; ++kk) {                                          \
        float4 a4 = *(const float4*)&As[kk][ty << 2];                          \
        float4 b4 = *(const float4*)&Bs[kk][tx << 2];                          \
        u64 a01 = pack2(a4.x, a4.y);                                           \
        u64 a23 = pack2(a4.z, a4.w);                                           \
        u64 bb;                                                                \
        bb = pack2(b4.x, b4.x);                                                \
        acc[0][0] = ffma2(a01, bb, acc[0][0]);                                 \
        acc[1][0] = ffma2(a23, bb, acc[1][0]);                                 \
        bb = pack2(b4.y, b4.y);                                                \
        acc[0][1] = ffma2(a01, bb, acc[0][1]);                                 \
        acc[1][1] = ffma2(a23, bb, acc[1][1]);                                 \
        bb = pack2(b4.z, b4.z);                                                \
        acc[0][2] = ffma2(a01, bb, acc[0][2]);                                 \
        acc[1][2] = ffma2(a23, bb, acc[1][2]);                                 \
        bb = pack2(b4.w, b4.w);                                                \
        acc[0][3] = ffma2(a01, bb, acc[0][3]);                                 \
        acc[1][3] = ffma2(a23, bb, acc[1][3]);                                 \
    }

#define GEMM_NN(Aptr, lda, Bptr, ldb, Ktot) {                                  \
    float4 pa = *(const float4*)((Aptr) + (size_t)ar * (lda) + ac);            \
    float4 pb = *(const float4*)((Bptr) + (size_t)br * (ldb) + bc);            \
    for (int kt = 0; kt < (Ktot); kt += 16) {                                  \
        As[ac+0][ar] = pa.x; As[ac+1][ar] = pa.y;                              \
        As[ac+2][ar] = pa.z; As[ac+3][ar] = pa.w;                              \
        *(float4*)&Bs[br][bc] = pb;                                            \
        __syncthreads();                                                       \
        if (kt + 16 < (Ktot)) {                                                \
            pa = *(const float4*)((Aptr) + (size_t)ar * (lda) + kt + 16 + ac); \
            pb = *(const float4*)((Bptr) + (size_t)(kt + 16 + br) * (ldb) + bc); \
        }                                                                      \
        INNER16                                                                \
        __syncthreads();                                                       \
    } }

#define GEMM_NT(Aptr, lda, Bptr, ldb, Ktot) {                                  \
    float4 pa = *(const float4*)((Aptr) + (size_t)ar * (lda) + ac);            \
    float4 pb = *(const float4*)((Bptr) + (size_t)ar * (ldb) + ac);            \
    for (int kt = 0; kt < (Ktot); kt += 16) {                                  \
        As[ac+0][ar] = pa.x; As[ac+1][ar] = pa.y;                              \
        As[ac+2][ar] = pa.z; As[ac+3][ar] = pa.w;                              \
        Bs[ac+0][ar] = pb.x; Bs[ac+1][ar] = pb.y;                              \
        Bs[ac+2][ar] = pb.z; Bs[ac+3][ar] = pb.w;                              \
        __syncthreads();                                                       \
        if (kt + 16 < (Ktot)) {                                                \
            pa = *(const float4*)((Aptr) + (size_t)ar * (lda) + kt + 16 + ac); \
            pb = *(const float4*)((Bptr) + (size_t)ar * (ldb) + kt + 16 + ac); \
        }                                                                      \
        INNER16                                                                \
        __syncthreads();                                                       \
    } }

#define GEMM_EPI                                                               \
    float rowv[4][4];                                                          \
    _Pragma("unroll")                                                          \
    for (int c = 0; c < 4; ++c) {                                              \
        float2 v0 = unpk(acc[0][c]);                                           \
        float2 v1 = unpk(acc[1][c]);                                           \
        rowv[0][c] = v0.x; rowv[1][c] = v0.y;                                  \
        rowv[2][c] = v1.x; rowv[3][c] = v1.y;                                  \
    }

// weight convert + transpose + split: src [K,N] fp32 -> dst [N,K] bf16 hi/lo.
// which: 1=w1, 2=w2. dst selected IN DEVICE CODE (ATS host-shadow pitfall).
__global__ void k_convw(const float* srcA, const float* srcB, int K, int N, int which) {
    int z = blockIdx.z;
    int e = z / NLAY, j = z % NLAY;
    const float* src = (e ? srcB : srcA) + (size_t)j * K * N;
    size_t doff = (size_t)j * K * N;
    __nv_bfloat16* hi = (which == 1) ? g_w1_hi[e] + doff : g_w2_hi[e] + doff;
    __nv_bfloat16* lo = (which == 1) ? g_w1_lo[e] + doff : g_w2_lo[e] + doff;

    __shared__ float tile[32][33];
    int n0 = blockIdx.x * 32, k0 = blockIdx.y * 32;
    int tx = threadIdx.x, ty = threadIdx.y;
#pragma unroll
    for (int r = 0; r < 32; r += 8)
        tile[ty + r][tx] = src[(size_t)(k0 + ty + r) * N + n0 + tx];
    __syncthreads();
#pragma unroll
    for (int r = 0; r < 32; r += 8) {
        float x = tile[tx][ty + r];
        size_t o = (size_t)(n0 + ty + r) * K + k0 + tx;
        split1(x, hi, lo, o);
    }
}

// ---------- WMMA GEMM (validated): C[128x64] = act @ Wt^T, bf16x3 split ----------
// mode 2: w1 (A = h split, relu -> mid split), z = e
// mode 3: w2 split-K: z = kc*2 + e, chunk K=512, partial -> g_ffpart[e][kc]
// mode 5: pk-scores (A = (q+v) split [512x512], B = pk split [1536x512]) -> scores*scale
__global__ void __launch_bounds__(256) k_tc(int mode, int j) {
    __shared__ __align__(16) char smem_raw[36864];
    __nv_bfloat16 (*sAh)[40] = (__nv_bfloat16(*)[40])(smem_raw);
    __nv_bfloat16 (*sAl)[40] = (__nv_bfloat16(*)[40])(smem_raw + 10240);
    __nv_bfloat16 (*sBh)[40] = (__nv_bfloat16(*)[40])(smem_raw + 20480);
    __nv_bfloat16 (*sBl)[40] = (__nv_bfloat16(*)[40])(smem_raw + 25600);

    const int t = threadIdx.x;
    const int e = blockIdx.z & 1;
    const int kc = blockIdx.z >> 1;
    const int nb = blockIdx.x;
    const int row0 = blockIdx.y << 7;
    const int lane = t & 31, w = t >> 5;
    const int wm = w & 3, wn = w >> 2;

    const __nv_bfloat16 *Ah, *Al, *Bh, *Bl;
    int Kld;
    if (mode == 2) {
        Ah = g_hhi[e]; Al = g_hlo[e];
        size_t woff = ((size_t)j * 2048 + nb * 64) * 512;
        Bh = g_w1_hi[e] + woff; Bl = g_w1_lo[e] + woff; Kld = 512;
    } else if (mode == 3) {
        Ah = g_midhi[e]; Al = g_midlo[e];
        size_t woff = ((size_t)j * 512 + nb * 64) * 2048;
        Bh = g_w2_hi[e] + woff; Bl = g_w2_lo[e] + woff; Kld = 2048;
    } else {
        Ah = g_qvhi[e]; Al = g_qvlo[e];
        size_t boff = (size_t)nb * 64 * 512;
        Bh = g_pkhi[e][j] + boff; Bl = g_pklo[e][j] + boff; Kld = 512;
    }
    const int k0 = kc * 512;
    Ah += (size_t)row0 * Kld + k0;
    Al += (size_t)row0 * Kld + k0;
    Bh += k0;
    Bl += k0;

    wmma::fragment<wmma::accumulator, 16, 16, 16, float> facc[2][2];
#pragma unroll
    for (int i = 0; i < 2; ++i)
#pragma unroll
        for (int jj = 0; jj < 2; ++jj)
            wmma::fill_fragment(facc[i][jj], 0.0f);

    for (int kt = 0; kt < 512; kt += 32) {
#pragma unroll
        for (int i = 0; i < 2; ++i) {
            int idx = t + i * 256;
            int r = idx >> 2, s = idx & 3;
            *(uint4*)&sAh[r][s * 8] = *(const uint4*)(Ah + (size_t)r * Kld + kt + s * 8);
            *(uint4*)&sAl[r][s * 8] = *(const uint4*)(Al + (size_t)r * Kld + kt + s * 8);
        }
        {
            int r = t >> 2, s = t & 3;
            *(uint4*)&sBh[r][s * 8] = *(const uint4*)(Bh + (size_t)r * Kld + kt + s * 8);
            *(uint4*)&sBl[r][s * 8] = *(const uint4*)(Bl + (size_t)r * Kld + kt + s * 8);
        }
        __syncthreads();

#pragma unroll
        for (int kk = 0; kk < 32; kk += 16) {
            wmma::fragment<wmma::matrix_a, 16, 16, 16, __nv_bfloat16, wmma::row_major> fAh, fAl;
            wmma::fragment<wmma::matrix_b, 16, 16, 16, __nv_bfloat16, wmma::col_major> fBh, fBl;
#pragma unroll
            for (int i = 0; i < 2; ++i) {
                wmma::load_matrix_sync(fAh, &sAh[(wm << 5) + (i << 4)][kk], 40);
                wmma::load_matrix_sync(fAl, &sAl[(wm << 5) + (i << 4)][kk], 40);
#pragma unroll
                for (int jj = 0; jj < 2; ++jj) {
                    wmma::load_matrix_sync(fBh, &sBh[(wn << 5) + (jj << 4)][kk], 40);
                    wmma::load_matrix_sync(fBl, &sBl[(wn << 5) + (jj << 4)][kk], 40);
                    wmma::mma_sync(facc[i][jj], fAh, fBh, facc[i][jj]);
                    wmma::mma_sync(facc[i][jj], fAh, fBl, facc[i][jj]);
                    wmma::mma_sync(facc[i][jj], fAl, fBh, facc[i][jj]);
                }
            }
        }
        __syncthreads();
    }

    float* sCw = (float*)smem_raw + w * (32 * 36);
#pragma unroll
    for (int i = 0; i < 2; ++i)
#pragma unroll
        for (int jj = 0; jj < 2; ++jj)
            wmma::store_matrix_sync(sCw + (i * 16) * 36 + jj * 16, facc[i][jj], 36,
                                    wmma::mem_row_major);
    __syncwarp();

    const int m = row0 + (wm << 5) + lane;
    if (mode == 2) {
        size_t o = (size_t)m * FFD + (nb << 6) + (wn << 5);
#pragma unroll
        for (int c = 0; c < 32; ++c) {
            float v = sCw[lane * 36 + c];
            split1(fmaxf(v, 0.f), g_midhi[e], g_midlo[e], o + c);
        }
    } else if (mode == 3) {
        float* P = g_ffpart[e][kc] + (size_t)m * 512 + (nb << 6) + (wn << 5);
#pragma unroll
        for (int c = 0; c < 32; ++c) P[c] = sCw[lane * 36 + c];
    } else {
        const float scale = 0.04419417382415922f;
        size_t o = (size_t)m * FULLN + (nb << 6) + (wn << 5);
#pragma unroll
        for (int c = 0; c < 32; ++c)
            g_scores[e][o + c] = sCw[lane * 36 + c] * scale;
    }
}

// ---------------- init: sinusoid table (flipped) ----------------
__global__ void k_R() {
    int i = blockIdx.x;
    int pos = FULLN - 1 - i;
    for (int dd = threadIdx.x; dd < 512; dd += 256) {
        int i2 = dd >> 1;
        float denom = powf(10000.0f, (float)(2 * i2) / 512.0f);
        double a = (double)((float)pos / denom);
        g_R[(size_t)i * 512 + dd] = (dd & 1) ? (float)cos(a) : (float)sin(a);
    }
}

// pk[e][j] = R @ Wr_j -> bf16 splits (static per launch; no ping-pong, no shift)
__global__ void __launch_bounds__(256) k_gemm_pk(const float* Wa, const float* Wb) {
    int z = blockIdx.z;
    int e = z / NLAY, layer = z % NLAY;
    GEMM_DECL
    const float* A = g_R + (size_t)row0 * 512;
    const float* B = (e ? Wb : Wa) + ((size_t)layer * 4 + 3) * 262144 + col0;
    GEMM_NN(A, 512, B, 512, 512)
    GEMM_EPI
#pragma unroll
    for (int i = 0; i < 4; ++i) {
        size_t o = (size_t)(row0 + (ty << 2) + i) * 512 + col0 + (tx << 2);
#pragma unroll
        for (int c = 0; c < 4; ++c)
            split1(rowv[i][c], g_pkhi[e][layer], g_pklo[e][layer], o + c);
    }
}

// state = emb[token]
__global__ void k_embed(const int* src, const float* emb, int s) {
    int e = blockIdx.y, m = blockIdx.x;
    int gpos = s * SEGN + m;
    int tok = e ? src[4095 - gpos] : src[gpos];
    const float4* sr = (const float4*)(emb + (size_t)tok * 512);
    float4* dst = (float4*)(g_state[e] + (size_t)m * 512);
    dst[threadIdx.x] = sr[threadIdx.x];
}

// shift cached k/v: buf[prev] rows 512..1536 -> buf[cur] rows 0..1024 (both ld 512)
__global__ void k_shift(int prev, int cur) {
    int e = blockIdx.z;
    int l = blockIdx.y >> 1, w = blockIdx.y & 1;
    int i = blockIdx.x * 256 + threadIdx.x;
    int row = i >> 7;
    int c4 = (i & 127) << 2;
    float* B = w ? g_vbuf[e][l][cur] : g_kbuf[e][l][cur];
    const float* S = w ? g_vbuf[e][l][prev] : g_kbuf[e][l][prev];
    float4 v = *(const float4*)&S[(size_t)(row + 512) * 512 + c4];
    *(float4*)&B[(size_t)row * 512 + c4] = v;
}

// merged q/k/v for CURRENT segment (R4 FFMA2 core)
// mat 0: Apu = q+u (fp32) and split(q+v); mat 1: k -> kbuf; mat 2: v -> vbuf
__global__ void __launch_bounds__(256) k_gemm_qkv(const float* Wa, const float* Wb,
                                                  const float* uva, const float* uvb,
                                                  int j, int buf) {
    int e = blockIdx.z;
    GEMM_DECL
    const int mat = col0 >> 9, n0 = col0 & 511;
    const float* A = g_state[e] + (size_t)row0 * 512;
    const float* B = (e ? Wb : Wa) + ((size_t)j * 4 + mat) * 262144 + n0;
    GEMM_NN(A, 512, B, 512, 512)
    GEMM_EPI
    if (mat == 0) {
        const float* uv = e ? uvb : uva;
#pragma unroll
        for (int i = 0; i < 4; ++i) {
            int m = row0 + (ty << 2) + i;
            int n = n0 + (tx << 2);
            size_t o = (size_t)m * 512 + n;
            float4 o1 = make_float4(rowv[i][0] + uv[n],     rowv[i][1] + uv[n + 1],
                                    rowv[i][2] + uv[n + 2], rowv[i][3] + uv[n + 3]);
            *(float4*)&g_Apu[e][o] = o1;
#pragma unroll
            for (int c = 0; c < 4; ++c)
                split1(rowv[i][c] + uv[512 + n + c], g_qvhi[e], g_qvlo[e], o + c);
        }
    } else if (mat == 1) {
        float* C = g_kbuf[e][j][buf];
#pragma unroll
        for (int i = 0; i < 4; ++i) {
            float4 o = make_float4(rowv[i][0], rowv[i][1], rowv[i][2], rowv[i][3]);
            *(float4*)&C[(size_t)(1024 + row0 + (ty << 2) + i) * 512 + n0 + (tx << 2)] = o;
        }
    } else {
        float* C = g_vbuf[e][j][buf];
#pragma unroll
        for (int i = 0; i < 4; ++i) {
            float4 o = make_float4(rowv[i][0], rowv[i][1], rowv[i][2], rowv[i][3]);
            *(float4*)&C[(size_t)(1024 + row0 + (ty << 2) + i) * 512 + n0 + (tx << 2)] = o;
        }
    }
}

// scores += Apu @ k^T * scale   (pk term already in g_scores from k_tc mode 5)
__global__ void __launch_bounds__(256) k_gemm_scores(int layer, int buf) {
    int e = blockIdx.z;
    GEMM_DECL
    const float* A = g_Apu[e] + (size_t)row0 * 512;
    const float* B = g_kbuf[e][layer][buf] + (size_t)col0 * 512;
    GEMM_NT(A, 512, B, 512, 512)
    GEMM_EPI
    const float scale = 0.04419417382415922f;
    float* C = g_scores[e];
#pragma unroll
    for (int i = 0; i < 4; ++i) {
        size_t o = (size_t)(row0 + (ty << 2) + i) * FULLN + col0 + (tx << 2);
        float4 prev = *(const float4*)&C[o];
        float4 out = make_float4(prev.x + rowv[i][0] * scale, prev.y + rowv[i][1] * scale,
                                 prev.z + rowv[i][2] * scale, prev.w + rowv[i][3] * scale);
        *(float4*)&C[o] = out;
    }
}

// row softmax over [vstart, 1536); zeros below
__global__ void k_softmax(int vstart) {
    int e = blockIdx.y, tid = threadIdx.x;
    float* s = g_scores[e] + (size_t)blockIdx.x * FULLN;
    __shared__ float red[256];
    float mx = -3.0e38f;
    for (int c = vstart + tid; c < FULLN; c += 256) mx = fmaxf(mx, s[c]);
    red[tid] = mx; __syncthreads();
    for (int o = 128; o; o >>= 1) { if (tid < o) red[tid] = fmaxf(red[tid], red[tid + o]); __syncthreads(); }
    mx = red[0]; __syncthreads();
    float sum = 0.f;
    for (int c = vstart + tid; c < FULLN; c += 256) { float v = expf(s[c] - mx); s[c] = v; sum += v; }
    red[tid] = sum; __syncthreads();
    for (int o = 128; o; o >>= 1) { if (tid < o) red[tid] += red[tid + o]; __syncthreads(); }
    float inv = 1.f / red[0];
    for (int c = tid; c < vstart; c += 256) s[c] = 0.f;
    for (int c = vstart + tid; c < FULLN; c += 256) s[c] *= inv;
}

// av split-K x3: z = kc*2 + e, K chunk 512, partial -> g_ffpart[e][kc]
__global__ void __launch_bounds__(256) k_gemm_av(int layer, int buf) {
    int e = blockIdx.z & 1, kc = blockIdx.z >> 1;
    GEMM_DECL
    const float* A = g_scores[e] + (size_t)row0 * FULLN + kc * 512;
    const float* B = g_vbuf[e][layer][buf] + (size_t)(kc * 512) * 512 + col0;
    GEMM_NN(A, FULLN, B, 512, 512)
    GEMM_EPI
    float* P = g_ffpart[e][kc];
#pragma unroll
    for (int i = 0; i < 4; ++i) {
        float4 o = make_float4(rowv[i][0], rowv[i][1], rowv[i][2], rowv[i][3]);
        *(float4*)&P[(size_t)(row0 + (ty << 2) + i) * 512 + col0 + (tx << 2)] = o;
    }
}

// av = (p0 + p1) + p2  (fixed order)
__global__ void k_avred() {
    int e = blockIdx.y, m = blockIdx.x, c = threadIdx.x;
    size_t o = (size_t)m * 512;
#pragma unroll
    for (int half = 0; half < 2; ++half) {
        int cc = c + half * 256;
        g_av[e][o + cc] = (g_ffpart[e][0][o + cc] + g_ffpart[e][1][o + cc])
                          + g_ffpart[e][2][o + cc];
    }
}

// wo split-K x2: z = kc*2 + e, K chunk 256, partial -> g_ffpart[e][kc]
__global__ void __launch_bounds__(256) k_gemm_wo(const float* Wa, const float* Wb, int layer) {
    int e = blockIdx.z & 1, kc = blockIdx.z >> 1;
    GEMM_DECL
    const float* A = g_av[e] + (size_t)row0 * 512 + kc * 256;
    const float* B = (e ? Wb : Wa) + (size_t)layer * 262144 + (size_t)(kc * 256) * 512 + col0;
    GEMM_NN(A, 512, B, 512, 256)
    GEMM_EPI
    float* P = g_ffpart[e][kc];
#pragma unroll
    for (int i = 0; i < 4; ++i) {
        float4 o = make_float4(rowv[i][0], rowv[i][1], rowv[i][2], rowv[i][3]);
        *(float4*)&P[(size_t)(row0 + (ty << 2) + i) * 512 + col0 + (tx << 2)] = o;
    }
}

// layernorm (reduction folded in).
// mode 0: x = state + p0 + p1 (wo partials) -> g_h (+ h split for w1)
// mode 1: x = h + (((p0+p1)+p2)+p3) (w2 partials) -> g_state
__global__ void k_ln(const float* lnA, const float* lnB, int layer, int mode) {
    int e = blockIdx.y, row = blockIdx.x, tid = threadIdx.x;
    size_t o = (size_t)row * 512;
    float x0, x1;
    if (mode == 0) {
        x0 = g_state[e][o + tid]       + g_ffpart[e][0][o + tid]       + g_ffpart[e][1][o + tid];
        x1 = g_state[e][o + tid + 256] + g_ffpart[e][0][o + tid + 256] + g_ffpart[e][1][o + tid + 256];
    } else {
        x0 = g_h[e][o + tid] + (((g_ffpart[e][0][o + tid] + g_ffpart[e][1][o + tid])
              + g_ffpart[e][2][o + tid]) + g_ffpart[e][3][o + tid]);
        x1 = g_h[e][o + tid + 256] + (((g_ffpart[e][0][o + tid + 256] + g_ffpart[e][1][o + tid + 256])
              + g_ffpart[e][2][o + tid + 256]) + g_ffpart[e][3][o + tid + 256]);
    }
    const float* ln = (e ? lnB : lnA) + ((size_t)layer * 4 + 2 * mode) * 512;
    __shared__ float red[256];
    red[tid] = x0 + x1; __syncthreads();
    for (int s = 128; s; s >>= 1) { if (tid < s) red[tid] += red[tid + s]; __syncthreads(); }
    float mu = red[0] * (1.f / 512.f); __syncthreads();
    float d0 = x0 - mu, d1 = x1 - mu;
    red[tid] = d0 * d0 + d1 * d1; __syncthreads();
    for (int s = 128; s; s >>= 1) { if (tid < s) red[tid] += red[tid + s]; __syncthreads(); }
    float r = rsqrtf(red[0] * (1.f / 512.f) + 1e-5f);
    float o0 = d0 * r * ln[tid] + ln[512 + tid];
    float o1 = d1 * r * ln[tid + 256] + ln[512 + tid + 256];
    float* out = mode ? g_state[e] : g_h[e];
    out[o + tid] = o0;
    out[o + tid + 256] = o1;
    if (mode == 0) {
        split1(o0, g_hhi[e], g_hlo[e], o + tid);
        split1(o1, g_hhi[e], g_hlo[e], o + tid + 256);
    }
}

// last-layer LN2 (mode-1 input) -> output with fwd/rev mapping
__global__ void k_ln_final(const float* lnA, const float* lnB, int layer, int s, float* out) {
    int e = blockIdx.y, row = blockIdx.x, tid = threadIdx.x;
    size_t o = (size_t)row * 512;
    float x0 = g_h[e][o + tid] + (((g_ffpart[e][0][o + tid] + g_ffpart[e][1][o + tid])
              + g_ffpart[e][2][o + tid]) + g_ffpart[e][3][o + tid]);
    float x1 = g_h[e][o + tid + 256] + (((g_ffpart[e][0][o + tid + 256] + g_ffpart[e][1][o + tid + 256])
              + g_ffpart[e][2][o + tid + 256]) + g_ffpart[e][3][o + tid + 256]);
    const float* ln = (e ? lnB : lnA) + ((size_t)layer * 4 + 2) * 512;
    __shared__ float red[256];
    red[tid] = x0 + x1; __syncthreads();
    for (int sft = 128; sft; sft >>= 1) { if (tid < sft) red[tid] += red[tid + sft]; __syncthreads(); }
    float mu = red[0] * (1.f / 512.f); __syncthreads();
    float d0 = x0 - mu, d1 = x1 - mu;
    red[tid] = d0 * d0 + d1 * d1; __syncthreads();
    for (int sft = 128; sft; sft >>= 1) { if (tid < sft) red[tid] += red[tid + sft]; __syncthreads(); }
    float r = rsqrtf(red[0] * (1.f / 512.f) + 1e-5f);
    int g = s * SEGN + row;
    float* dst = e ? (out + (size_t)(4095 - g) * 1024 + 512) : (out + (size_t)g * 1024);
    dst[tid]       = d0 * r * ln[tid]       + ln[512 + tid];
    dst[tid + 256] = d1 * r * ln[tid + 256] + ln[512 + tid + 256];
}

// ---------------- host orchestration (graph-capturable: launches only) ----------------
extern "C" void kernel_launch(void* const* d_in, const int* in_sizes, int n_in,
                              void* d_out, int out_size) {
    const int*   src  = (const int*)d_in[0];
    const float* emb  = (const float*)d_in[2];
    const float* Wq_a = (const float*)d_in[3];
    const float* Wo_a = (const float*)d_in[4];
    const float* W1_a = (const float*)d_in[5];
    const float* W2_a = (const float*)d_in[6];
    const float* ln_a = (const float*)d_in[7];
    const float* uv_a = (const float*)d_in[8];
    const float* Wq_b = (const float*)d_in[9];
    const float* Wo_b = (const float*)d_in[10];
    const float* W1_b = (const float*)d_in[11];
    const float* W2_b = (const float*)d_in[12];
    const float* ln_b = (const float*)d_in[13];
    const float* uv_b = (const float*)d_in[14];
    float* out = (float*)d_out;

    k_R<<<FULLN, 256>>>();
    k_gemm_pk<<<dim3(8, 24, 12), 256>>>(Wq_a, Wq_b);

    // weight conversion for the tensor-core FF pair (dst selected in device code)
    dim3 cb(32, 8);
    k_convw<<<dim3(64, 16, 12), cb>>>(W1_a, W1_b, 512, 2048, 1);
    k_convw<<<dim3(16, 64, 12), cb>>>(W2_a, W2_b, 2048, 512, 2);

    for (int s = 0; s < NSEGS; ++s) {
        int buf = s & 1, prev = buf ^ 1;
        if (s > 0) k_shift<<<dim3(512, 12, 2), 256>>>(prev, buf);
        k_embed<<<dim3(512, 2), 128>>>(src, emb, s);
        int vstart = 1024 - (s < 2 ? s : 2) * 512;
        for (int j = 0; j < NLAY; ++j) {
            k_gemm_qkv   <<<dim3(24, 8, 2), 256>>>(Wq_a, Wq_b, uv_a, uv_b, j, buf);
            k_tc         <<<dim3(24, 4, 2), 256>>>(5, j);          // pk-term of scores
            k_gemm_scores<<<dim3(24, 8, 2), 256>>>(j, buf);        // += k-term
            k_softmax    <<<dim3(512, 2),   256>>>(vstart);
            k_gemm_av    <<<dim3(8, 8, 6),  256>>>(j, buf);        // split-K x3
            k_avred      <<<dim3(512, 2),   256>>>();
            k_gemm_wo    <<<dim3(8, 8, 4),  256>>>(Wo_a, Wo_b, j); // split-K x2
            k_ln         <<<dim3(512, 2),   256>>>(ln_a, ln_b, j, 0);
            k_tc         <<<dim3(32, 4, 2), 256>>>(2, j);
            k_tc         <<<dim3(8, 4, 8),  256>>>(3, j);          // split-K x4
            if (j < NLAY - 1) k_ln<<<dim3(512, 2), 256>>>(ln_a, ln_b, j, 1);
            else              k_ln_final<<<dim3(512, 2), 256>>>(ln_a, ln_b, j, s, out);
        }
    }
}

// round 16
// speedup vs baseline: 1.0045x; 1.0045x over previous
#include <cuda_runtime.h>
#include <cuda_bf16.h>
#include <mma.h>
#include <math.h>
#include <stdint.h>

#define SEGN 512
#define NLAY 6
#define NSEGS 8
#define FFD 2048
#define FULLN 1536

typedef unsigned long long u64;
using namespace nvcuda;

// ---------------- packed fp32 math (Blackwell FFMA2, PTX-only) ----------------
__device__ __forceinline__ u64 ffma2(u64 a, u64 b, u64 c) {
    u64 d;
    asm("fma.rn.f32x2 %0, %1, %2, %3;" : "=l"(d) : "l"(a), "l"(b), "l"(c));
    return d;
}
__device__ __forceinline__ u64 pack2(float x, float y) {
    u64 d;
    asm("mov.b64 %0, {%1, %2};" : "=l"(d)
        : "r"(__float_as_uint(x)), "r"(__float_as_uint(y)));
    return d;
}
__device__ __forceinline__ float2 unpk(u64 a) {
    unsigned lo, hi;
    asm("mov.b64 {%0, %1}, %2;" : "=r"(lo), "=r"(hi) : "l"(a));
    return make_float2(__uint_as_float(lo), __uint_as_float(hi));
}

// ---------------- fp32 scratch ----------------
__device__ float g_R[FULLN * 512];
__device__ float g_state[2][SEGN * 512];
__device__ float g_Ap[2][SEGN * 1024];
__device__ float g_kbuf[2][NLAY][2][FULLN * 1024];   // ping-pong [k | pk]
__device__ float g_vbuf[2][NLAY][2][FULLN * 512];    // ping-pong v
__device__ float g_scores[2][SEGN * FULLN];
__device__ float g_h[2][SEGN * 512];
__device__ float g_ffpart[2][4][SEGN * 512];         // split-K partials (av / w2)
__device__ float g_wopart[2][2][SEGN * 512];         // split-K partials (wo)

// ---------------- bf16 split scratch (tensor-core path: W1/W2 only) ----------------
__device__ __nv_bfloat16 g_w1_hi[2][6 * 2048 * 512];   // [j][2048 n][512 k]
__device__ __nv_bfloat16 g_w1_lo[2][6 * 2048 * 512];
__device__ __nv_bfloat16 g_w2_hi[2][6 * 512 * 2048];   // [j][512 n][2048 k]
__device__ __nv_bfloat16 g_w2_lo[2][6 * 512 * 2048];
__device__ __nv_bfloat16 g_hhi[2][SEGN * 512],   g_hlo[2][SEGN * 512];
__device__ __nv_bfloat16 g_midhi[2][SEGN * FFD], g_midlo[2][SEGN * FFD];

__device__ __forceinline__ void split1(float x, __nv_bfloat16* hi, __nv_bfloat16* lo, size_t i) {
    __nv_bfloat16 h = __float2bfloat16_rn(x);
    hi[i] = h;
    lo[i] = __float2bfloat16_rn(x - __bfloat162float(h));
}

// ---------------- R4 FFMA2 GEMM core (BK16, reg prefetch) ----------------
#define GEMM_DECL                                                              \
    __shared__ float As[16][68];                                               \
    __shared__ float Bs[16][68];                                               \
    u64 acc[2][4] = {{0ull,0ull,0ull,0ull},{0ull,0ull,0ull,0ull}};             \
    const int t  = threadIdx.x;                                                \
    const int tx = t & 15, ty = t >> 4;                                        \
    const int ar = t >> 2, ac = (t & 3) << 2;                                  \
    const int br = t >> 4, bc = (t & 15) << 2;                                 \
    const int row0 = blockIdx.y << 6, col0 = blockIdx.x << 6;                  \
    (void)br; (void)bc; (void)row0; (void)col0;

#define INNER16                                                                \
    _Pragma("unroll")                                                          \
    for (int kk = 0; kk < 16; ++kk) {                                          \
        float4 a4 = *(const float4*)&As[kk][ty << 2];                          \
        float4 b4 = *(const float4*)&Bs[kk][tx << 2];                          \
        u64 a01 = pack2(a4.x, a4.y);                                           \
        u64 a23 = pack2(a4.z, a4.w);                                           \
        u64 bb;                                                                \
        bb = pack2(b4.x, b4.x);                                                \
        acc[0][0] = ffma2(a01, bb, acc[0][0]);                                 \
        acc[1][0] = ffma2(a23, bb, acc[1][0]);                                 \
        bb = pack2(b4.y, b4.y);                                                \
        acc[0][1] = ffma2(a01, bb, acc[0][1]);                                 \
        acc[1][1] = ffma2(a23, bb, acc[1][1]);                                 \
        bb = pack2(b4.z, b4.z);                                                \
        acc[0][2] = ffma2(a01, bb, acc[0][2]);                                 \
        acc[1][2] = ffma2(a23, bb, acc[1][2]);                                 \
        bb = pack2(b4.w, b4.w);                                                \
        acc[0][3] = ffma2(a01, bb, acc[0][3]);                                 \
        acc[1][3] = ffma2(a23, bb, acc[1][3]);                                 \
    }

#define GEMM_NN(Aptr, lda, Bptr, ldb, Ktot) {                                  \
    float4 pa = *(const float4*)((Aptr) + (size_t)ar * (lda) + ac);            \
    float4 pb = *(const float4*)((Bptr) + (size_t)br * (ldb) + bc);            \
    for (int kt = 0; kt < (Ktot); kt += 16) {                                  \
        As[ac+0][ar] = pa.x; As[ac+1][ar] = pa.y;                              \
        As[ac+2][ar] = pa.z; As[ac+3][ar] = pa.w;                              \
        *(float4*)&Bs[br][bc] = pb;                                            \
        __syncthreads();                                                       \
        if (kt + 16 < (Ktot)) {                                                \
            pa = *(const float4*)((Aptr) + (size_t)ar * (lda) + kt + 16 + ac); \
            pb = *(const float4*)((Bptr) + (size_t)(kt + 16 + br) * (ldb) + bc); \
        }                                                                      \
        INNER16                                                                \
        __syncthreads();                                                       \
    } }

// A staged as fixed-order sum of three partial buffers (replaces k_avred)
#define LD3(off) \
    [&]{ float4 v0 = *(const float4*)((A0) + (off));                           \
         float4 v1 = *(const float4*)((A1) + (off));                           \
         float4 v2 = *(const float4*)((A2) + (off));                           \
         return make_float4((v0.x + v1.x) + v2.x, (v0.y + v1.y) + v2.y,        \
                            (v0.z + v1.z) + v2.z, (v0.w + v1.w) + v2.w); }()

#define GEMM_NN3(lda, Bptr, ldb, Ktot) {                                       \
    float4 pa = LD3((size_t)ar * (lda) + ac);                                  \
    float4 pb = *(const float4*)((Bptr) + (size_t)br * (ldb) + bc);            \
    for (int kt = 0; kt < (Ktot); kt += 16) {                                  \
        As[ac+0][ar] = pa.x; As[ac+1][ar] = pa.y;                              \
        As[ac+2][ar] = pa.z; As[ac+3][ar] = pa.w;                              \
        *(float4*)&Bs[br][bc] = pb;                                            \
        __syncthreads();                                                       \
        if (kt + 16 < (Ktot)) {                                                \
            pa = LD3((size_t)ar * (lda) + kt + 16 + ac);                       \
            pb = *(const float4*)((Bptr) + (size_t)(kt + 16 + br) * (ldb) + bc); \
        }                                                                      \
        INNER16                                                                \
        __syncthreads();                                                       \
    } }

#define GEMM_NT(Aptr, lda, Bptr, ldb, Ktot) {                                  \
    float4 pa = *(const float4*)((Aptr) + (size_t)ar * (lda) + ac);            \
    float4 pb = *(const float4*)((Bptr) + (size_t)ar * (ldb) + ac);            \
    for (int kt = 0; kt < (Ktot); kt += 16) {                                  \
        As[ac+0][ar] = pa.x; As[ac+1][ar] = pa.y;                              \
        As[ac+2][ar] = pa.z; As[ac+3][ar] = pa.w;                              \
        Bs[ac+0][ar] = pb.x; Bs[ac+1][ar] = pb.y;                              \
        Bs[ac+2][ar] = pb.z; Bs[ac+3][ar] = pb.w;                              \
        __syncthreads();                                                       \
        if (kt + 16 < (Ktot)) {                                                \
            pa = *(const float4*)((Aptr) + (size_t)ar * (lda) + kt + 16 + ac); \
            pb = *(const float4*)((Bptr) + (size_t)ar * (ldb) + kt + 16 + ac); \
        }                                                                      \
        INNER16                                                                \
        __syncthreads();                                                       \
    } }

#define GEMM_EPI                                                               \
    float rowv[4][4];                                                          \
    _Pragma("unroll")                                                          \
    for (int c = 0; c < 4; ++c) {                                              \
        float2 v0 = unpk(acc[0][c]);                                           \
        float2 v1 = unpk(acc[1][c]);                                           \
        rowv[0][c] = v0.x; rowv[1][c] = v0.y;                                  \
        rowv[2][c] = v1.x; rowv[3][c] = v1.y;                                  \
    }

// weight convert + transpose + split: src [K,N] fp32 -> dst [N,K] bf16 hi/lo.
// which: 1=w1, 2=w2. dst selected IN DEVICE CODE (ATS host-shadow pitfall).
__global__ void k_convw(const float* srcA, const float* srcB, int K, int N, int which) {
    int z = blockIdx.z;
    int e = z / NLAY, j = z % NLAY;
    const float* src = (e ? srcB : srcA) + (size_t)j * K * N;
    size_t doff = (size_t)j * K * N;
    __nv_bfloat16* hi = (which == 1) ? g_w1_hi[e] + doff : g_w2_hi[e] + doff;
    __nv_bfloat16* lo = (which == 1) ? g_w1_lo[e] + doff : g_w2_lo[e] + doff;

    __shared__ float tile[32][33];
    int n0 = blockIdx.x * 32, k0 = blockIdx.y * 32;
    int tx = threadIdx.x, ty = threadIdx.y;
#pragma unroll
    for (int r = 0; r < 32; r += 8)
        tile[ty + r][tx] = src[(size_t)(k0 + ty + r) * N + n0 + tx];
    __syncthreads();
#pragma unroll
    for (int r = 0; r < 32; r += 8) {
        float x = tile[tx][ty + r];
        size_t o = (size_t)(n0 + ty + r) * K + k0 + tx;
        split1(x, hi, lo, o);
    }
}

// ---------- WMMA GEMM (validated): C[128x64] = act @ Wt^T, bf16x3 split ----------
// mode 2: w1 (A = h split, relu -> mid split), z = e
// mode 3: w2 split-K: z = kc*2 + e, chunk K=512, partial -> g_ffpart[e][kc]
__global__ void __launch_bounds__(256) k_tc(int mode, int j) {
    __shared__ __align__(16) char smem_raw[36864];
    __nv_bfloat16 (*sAh)[40] = (__nv_bfloat16(*)[40])(smem_raw);
    __nv_bfloat16 (*sAl)[40] = (__nv_bfloat16(*)[40])(smem_raw + 10240);
    __nv_bfloat16 (*sBh)[40] = (__nv_bfloat16(*)[40])(smem_raw + 20480);
    __nv_bfloat16 (*sBl)[40] = (__nv_bfloat16(*)[40])(smem_raw + 25600);

    const int t = threadIdx.x;
    const int e = blockIdx.z & 1;
    const int kc = blockIdx.z >> 1;
    const int nb = blockIdx.x;
    const int row0 = blockIdx.y << 7;
    const int lane = t & 31, w = t >> 5;
    const int wm = w & 3, wn = w >> 2;

    const __nv_bfloat16 *Ah, *Al, *Bh, *Bl;
    int Kld;
    if (mode == 2) {
        Ah = g_hhi[e]; Al = g_hlo[e];
        size_t woff = ((size_t)j * 2048 + nb * 64) * 512;
        Bh = g_w1_hi[e] + woff; Bl = g_w1_lo[e] + woff; Kld = 512;
    } else {
        Ah = g_midhi[e]; Al = g_midlo[e];
        size_t woff = ((size_t)j * 512 + nb * 64) * 2048;
        Bh = g_w2_hi[e] + woff; Bl = g_w2_lo[e] + woff; Kld = 2048;
    }
    const int k0 = kc * 512;
    Ah += (size_t)row0 * Kld + k0;
    Al += (size_t)row0 * Kld + k0;
    Bh += k0;
    Bl += k0;

    wmma::fragment<wmma::accumulator, 16, 16, 16, float> facc[2][2];
#pragma unroll
    for (int i = 0; i < 2; ++i)
#pragma unroll
        for (int jj = 0; jj < 2; ++jj)
            wmma::fill_fragment(facc[i][jj], 0.0f);

    for (int kt = 0; kt < 512; kt += 32) {
#pragma unroll
        for (int i = 0; i < 2; ++i) {
            int idx = t + i * 256;
            int r = idx >> 2, s = idx & 3;
            *(uint4*)&sAh[r][s * 8] = *(const uint4*)(Ah + (size_t)r * Kld + kt + s * 8);
            *(uint4*)&sAl[r][s * 8] = *(const uint4*)(Al + (size_t)r * Kld + kt + s * 8);
        }
        {
            int r = t >> 2, s = t & 3;
            *(uint4*)&sBh[r][s * 8] = *(const uint4*)(Bh + (size_t)r * Kld + kt + s * 8);
            *(uint4*)&sBl[r][s * 8] = *(const uint4*)(Bl + (size_t)r * Kld + kt + s * 8);
        }
        __syncthreads();

#pragma unroll
        for (int kk = 0; kk < 32; kk += 16) {
            wmma::fragment<wmma::matrix_a, 16, 16, 16, __nv_bfloat16, wmma::row_major> fAh, fAl;
            wmma::fragment<wmma::matrix_b, 16, 16, 16, __nv_bfloat16, wmma::col_major> fBh, fBl;
#pragma unroll
            for (int i = 0; i < 2; ++i) {
                wmma::load_matrix_sync(fAh, &sAh[(wm << 5) + (i << 4)][kk], 40);
                wmma::load_matrix_sync(fAl, &sAl[(wm << 5) + (i << 4)][kk], 40);
#pragma unroll
                for (int jj = 0; jj < 2; ++jj) {
                    wmma::load_matrix_sync(fBh, &sBh[(wn << 5) + (jj << 4)][kk], 40);
                    wmma::load_matrix_sync(fBl, &sBl[(wn << 5) + (jj << 4)][kk], 40);
                    wmma::mma_sync(facc[i][jj], fAh, fBh, facc[i][jj]);
                    wmma::mma_sync(facc[i][jj], fAh, fBl, facc[i][jj]);
                    wmma::mma_sync(facc[i][jj], fAl, fBh, facc[i][jj]);
                }
            }
        }
        __syncthreads();
    }

    float* sCw = (float*)smem_raw + w * (32 * 36);
#pragma unroll
    for (int i = 0; i < 2; ++i)
#pragma unroll
        for (int jj = 0; jj < 2; ++jj)
            wmma::store_matrix_sync(sCw + (i * 16) * 36 + jj * 16, facc[i][jj], 36,
                                    wmma::mem_row_major);
    __syncwarp();

    const int m = row0 + (wm << 5) + lane;
    if (mode == 2) {
        size_t o = (size_t)m * FFD + (nb << 6) + (wn << 5);
#pragma unroll
        for (int c = 0; c < 32; ++c) {
            float v = sCw[lane * 36 + c];
            split1(fmaxf(v, 0.f), g_midhi[e], g_midlo[e], o + c);
        }
    } else {
        float* P = g_ffpart[e][kc] + (size_t)m * 512 + (nb << 6) + (wn << 5);
#pragma unroll
        for (int c = 0; c < 32; ++c) P[c] = sCw[lane * 36 + c];
    }
}

// ---------------- init: sinusoid table (flipped) ----------------
__global__ void k_R() {
    int i = blockIdx.x;
    int pos = FULLN - 1 - i;
    for (int dd = threadIdx.x; dd < 512; dd += 256) {
        int i2 = dd >> 1;
        float denom = powf(10000.0f, (float)(2 * i2) / 512.0f);
        double a = (double)((float)pos / denom);
        g_R[(size_t)i * 512 + dd] = (dd & 1) ? (float)cos(a) : (float)sin(a);
    }
}

// pk[e][j] = R @ Wr_j  -> both ping-pong kbuf buffers, cols 512..1024
__global__ void __launch_bounds__(256) k_gemm_pk(const float* Wa, const float* Wb) {
    int z = blockIdx.z;
    int e = z / NLAY, layer = z % NLAY;
    GEMM_DECL
    const float* A = g_R + (size_t)row0 * 512;
    const float* B = (e ? Wb : Wa) + ((size_t)layer * 4 + 3) * 262144 + col0;
    GEMM_NN(A, 512, B, 512, 512)
    GEMM_EPI
#pragma unroll
    for (int i = 0; i < 4; ++i) {
        float4 o = make_float4(rowv[i][0], rowv[i][1], rowv[i][2], rowv[i][3]);
        size_t off = (size_t)(row0 + (ty << 2) + i) * 1024 + 512 + col0 + (tx << 2);
        *(float4*)&g_kbuf[e][layer][0][off] = o;
        *(float4*)&g_kbuf[e][layer][1][off] = o;
    }
}

// state = emb[token]
__global__ void k_embed(const int* src, const float* emb, int s) {
    int e = blockIdx.y, m = blockIdx.x;
    int gpos = s * SEGN + m;
    int tok = e ? src[4095 - gpos] : src[gpos];
    const float4* sr = (const float4*)(emb + (size_t)tok * 512);
    float4* dst = (float4*)(g_state[e] + (size_t)m * 512);
    dst[threadIdx.x] = sr[threadIdx.x];
}

// shift cached k/v: buf[prev] rows 512..1536 -> buf[cur] rows 0..1024
__global__ void k_shift(int prev, int cur) {
    int e = blockIdx.z;
    int l = blockIdx.y >> 1, w = blockIdx.y & 1;
    int i = blockIdx.x * 256 + threadIdx.x;
    int row = i >> 7;
    int c4 = (i & 127) << 2;
    if (w == 0) {
        float4 v = *(const float4*)&g_kbuf[e][l][prev][(size_t)(row + 512) * 1024 + c4];
        *(float4*)&g_kbuf[e][l][cur][(size_t)row * 1024 + c4] = v;
    } else {
        float4 v = *(const float4*)&g_vbuf[e][l][prev][(size_t)(row + 512) * 512 + c4];
        *(float4*)&g_vbuf[e][l][cur][(size_t)row * 512 + c4] = v;
    }
}

// merged q/k/v for CURRENT segment (R4 FFMA2, known good)
__global__ void __launch_bounds__(256) k_gemm_qkv(const float* Wa, const float* Wb,
                                                  const float* uva, const float* uvb,
                                                  int j, int buf) {
    int e = blockIdx.z;
    GEMM_DECL
    const int mat = col0 >> 9, n0 = col0 & 511;
    const float* A = g_state[e] + (size_t)row0 * 512;
    const float* B = (e ? Wb : Wa) + ((size_t)j * 4 + mat) * 262144 + n0;
    GEMM_NN(A, 512, B, 512, 512)
    GEMM_EPI
    if (mat == 0) {
        const float* uv = e ? uvb : uva;
        float* Ap = g_Ap[e];
#pragma unroll
        for (int i = 0; i < 4; ++i) {
            int m = row0 + (ty << 2) + i;
            int n = n0 + (tx << 2);
            float4 o1 = make_float4(rowv[i][0] + uv[n],     rowv[i][1] + uv[n + 1],
                                    rowv[i][2] + uv[n + 2], rowv[i][3] + uv[n + 3]);
            float4 o2 = make_float4(rowv[i][0] + uv[512 + n],     rowv[i][1] + uv[512 + n + 1],
                                    rowv[i][2] + uv[512 + n + 2], rowv[i][3] + uv[512 + n + 3]);
            *(float4*)&Ap[(size_t)m * 1024 + n] = o1;
            *(float4*)&Ap[(size_t)m * 1024 + 512 + n] = o2;
        }
    } else if (mat == 1) {
        float* C = g_kbuf[e][j][buf];
#pragma unroll
        for (int i = 0; i < 4; ++i) {
            float4 o = make_float4(rowv[i][0], rowv[i][1], rowv[i][2], rowv[i][3]);
            *(float4*)&C[(size_t)(1024 + row0 + (ty << 2) + i) * 1024 + n0 + (tx << 2)] = o;
        }
    } else {
        float* C = g_vbuf[e][j][buf];
#pragma unroll
        for (int i = 0; i < 4; ++i) {
            float4 o = make_float4(rowv[i][0], rowv[i][1], rowv[i][2], rowv[i][3]);
            *(float4*)&C[(size_t)(1024 + row0 + (ty << 2) + i) * 512 + n0 + (tx << 2)] = o;
        }
    }
}

// scores = Ap @ kbuf[buf]^T * scale
__global__ void __launch_bounds__(256) k_gemm_scores(int layer, int buf) {
    int e = blockIdx.z;
    GEMM_DECL
    const float* A = g_Ap[e] + (size_t)row0 * 1024;
    const float* B = g_kbuf[e][layer][buf] + (size_t)col0 * 1024;
    GEMM_NT(A, 1024, B, 1024, 1024)
    GEMM_EPI
    const float scale = 0.04419417382415922f;
    float* C = g_scores[e];
#pragma unroll
    for (int i = 0; i < 4; ++i) {
        float4 o = make_float4(rowv[i][0] * scale, rowv[i][1] * scale,
                               rowv[i][2] * scale, rowv[i][3] * scale);
        *(float4*)&C[(size_t)(row0 + (ty << 2) + i) * FULLN + col0 + (tx << 2)] = o;
    }
}

// row softmax over [vstart, 1536); zeros below
__global__ void k_softmax(int vstart) {
    int e = blockIdx.y, tid = threadIdx.x;
    float* s = g_scores[e] + (size_t)blockIdx.x * FULLN;
    __shared__ float red[256];
    float mx = -3.0e38f;
    for (int c = vstart + tid; c < FULLN; c += 256) mx = fmaxf(mx, s[c]);
    red[tid] = mx; __syncthreads();
    for (int o = 128; o; o >>= 1) { if (tid < o) red[tid] = fmaxf(red[tid], red[tid + o]); __syncthreads(); }
    mx = red[0]; __syncthreads();
    float sum = 0.f;
    for (int c = vstart + tid; c < FULLN; c += 256) { float v = expf(s[c] - mx); s[c] = v; sum += v; }
    red[tid] = sum; __syncthreads();
    for (int o = 128; o; o >>= 1) { if (tid < o) red[tid] += red[tid + o]; __syncthreads(); }
    float inv = 1.f / red[0];
    for (int c = tid; c < vstart; c += 256) s[c] = 0.f;
    for (int c = vstart + tid; c < FULLN; c += 256) s[c] *= inv;
}

// av split-K x3: z = kc*2 + e, K chunk 512, partial -> g_ffpart[e][kc]
__global__ void __launch_bounds__(256) k_gemm_av(int layer, int buf) {
    int e = blockIdx.z & 1, kc = blockIdx.z >> 1;
    GEMM_DECL
    const float* A = g_scores[e] + (size_t)row0 * FULLN + kc * 512;
    const float* B = g_vbuf[e][layer][buf] + (size_t)(kc * 512) * 512 + col0;
    GEMM_NN(A, FULLN, B, 512, 512)
    GEMM_EPI
    float* P = g_ffpart[e][kc];
#pragma unroll
    for (int i = 0; i < 4; ++i) {
        float4 o = make_float4(rowv[i][0], rowv[i][1], rowv[i][2], rowv[i][3]);
        *(float4*)&P[(size_t)(row0 + (ty << 2) + i) * 512 + col0 + (tx << 2)] = o;
    }
}

// wo split-K x2: A = (p0+p1)+p2 staged on the fly (replaces k_avred);
// partials -> g_wopart[e][kc] (separate from ffpart to avoid read/write overlap)
__global__ void __launch_bounds__(256) k_gemm_wo(const float* Wa, const float* Wb, int layer) {
    int e = blockIdx.z & 1, kc = blockIdx.z >> 1;
    GEMM_DECL
    const float* A0 = g_ffpart[e][0] + (size_t)row0 * 512 + kc * 256;
    const float* A1 = g_ffpart[e][1] + (size_t)row0 * 512 + kc * 256;
    const float* A2 = g_ffpart[e][2] + (size_t)row0 * 512 + kc * 256;
    const float* B = (e ? Wb : Wa) + (size_t)layer * 262144 + (size_t)(kc * 256) * 512 + col0;
    GEMM_NN3(512, B, 512, 256)
    GEMM_EPI
    float* P = g_wopart[e][kc];
#pragma unroll
    for (int i = 0; i < 4; ++i) {
        float4 o = make_float4(rowv[i][0], rowv[i][1], rowv[i][2], rowv[i][3]);
        *(float4*)&P[(size_t)(row0 + (ty << 2) + i) * 512 + col0 + (tx << 2)] = o;
    }
}

// layernorm (reduction folded in).
// mode 0: x = state + wop0 + wop1 -> g_h (+ h split for w1)
// mode 1: x = h + (((p0+p1)+p2)+p3) (w2 partials) -> g_state
__global__ void k_ln(const float* lnA, const float* lnB, int layer, int mode) {
    int e = blockIdx.y, row = blockIdx.x, tid = threadIdx.x;
    size_t o = (size_t)row * 512;
    float x0, x1;
    if (mode == 0) {
        x0 = g_state[e][o + tid]       + g_wopart[e][0][o + tid]       + g_wopart[e][1][o + tid];
        x1 = g_state[e][o + tid + 256] + g_wopart[e][0][o + tid + 256] + g_wopart[e][1][o + tid + 256];
    } else {
        x0 = g_h[e][o + tid] + (((g_ffpart[e][0][o + tid] + g_ffpart[e][1][o + tid])
              + g_ffpart[e][2][o + tid]) + g_ffpart[e][3][o + tid]);
        x1 = g_h[e][o + tid + 256] + (((g_ffpart[e][0][o + tid + 256] + g_ffpart[e][1][o + tid + 256])
              + g_ffpart[e][2][o + tid + 256]) + g_ffpart[e][3][o + tid + 256]);
    }
    const float* ln = (e ? lnB : lnA) + ((size_t)layer * 4 + 2 * mode) * 512;
    __shared__ float red[256];
    red[tid] = x0 + x1; __syncthreads();
    for (int s = 128; s; s >>= 1) { if (tid < s) red[tid] += red[tid + s]; __syncthreads(); }
    float mu = red[0] * (1.f / 512.f); __syncthreads();
    float d0 = x0 - mu, d1 = x1 - mu;
    red[tid] = d0 * d0 + d1 * d1; __syncthreads();
    for (int s = 128; s; s >>= 1) { if (tid < s) red[tid] += red[tid + s]; __syncthreads(); }
    float r = rsqrtf(red[0] * (1.f / 512.f) + 1e-5f);
    float o0 = d0 * r * ln[tid] + ln[512 + tid];
    float o1 = d1 * r * ln[tid + 256] + ln[512 + tid + 256];
    float* out = mode ? g_state[e] : g_h[e];
    out[o + tid] = o0;
    out[o + tid + 256] = o1;
    if (mode == 0) {
        split1(o0, g_hhi[e], g_hlo[e], o + tid);
        split1(o1, g_hhi[e], g_hlo[e], o + tid + 256);
    }
}

// last-layer LN2 (mode-1 input) -> output with fwd/rev mapping
__global__ void k_ln_final(const float* lnA, const float* lnB, int layer, int s, float* out) {
    int e = blockIdx.y, row = blockIdx.x, tid = threadIdx.x;
    size_t o = (size_t)row * 512;
    float x0 = g_h[e][o + tid] + (((g_ffpart[e][0][o + tid] + g_ffpart[e][1][o + tid])
              + g_ffpart[e][2][o + tid]) + g_ffpart[e][3][o + tid]);
    float x1 = g_h[e][o + tid + 256] + (((g_ffpart[e][0][o + tid + 256] + g_ffpart[e][1][o + tid + 256])
              + g_ffpart[e][2][o + tid + 256]) + g_ffpart[e][3][o + tid + 256]);
    const float* ln = (e ? lnB : lnA) + ((size_t)layer * 4 + 2) * 512;
    __shared__ float red[256];
    red[tid] = x0 + x1; __syncthreads();
    for (int sft = 128; sft; sft >>= 1) { if (tid < sft) red[tid] += red[tid + sft]; __syncthreads(); }
    float mu = red[0] * (1.f / 512.f); __syncthreads();
    float d0 = x0 - mu, d1 = x1 - mu;
    red[tid] = d0 * d0 + d1 * d1; __syncthreads();
    for (int sft = 128; sft; sft >>= 1) { if (tid < sft) red[tid] += red[tid + sft]; __syncthreads(); }
    float r = rsqrtf(red[0] * (1.f / 512.f) + 1e-5f);
    int g = s * SEGN + row;
    float* dst = e ? (out + (size_t)(4095 - g) * 1024 + 512) : (out + (size_t)g * 1024);
    dst[tid]       = d0 * r * ln[tid]       + ln[512 + tid];
    dst[tid + 256] = d1 * r * ln[tid + 256] + ln[512 + tid + 256];
}

// ---------------- host orchestration (graph-capturable: launches only) ----------------
extern "C" void kernel_launch(void* const* d_in, const int* in_sizes, int n_in,
                              void* d_out, int out_size) {
    const int*   src  = (const int*)d_in[0];
    const float* emb  = (const float*)d_in[2];
    const float* Wq_a = (const float*)d_in[3];
    const float* Wo_a = (const float*)d_in[4];
    const float* W1_a = (const float*)d_in[5];
    const float* W2_a = (const float*)d_in[6];
    const float* ln_a = (const float*)d_in[7];
    const float* uv_a = (const float*)d_in[8];
    const float* Wq_b = (const float*)d_in[9];
    const float* Wo_b = (const float*)d_in[10];
    const float* W1_b = (const float*)d_in[11];
    const float* W2_b = (const float*)d_in[12];
    const float* ln_b = (const float*)d_in[13];
    const float* uv_b = (const float*)d_in[14];
    float* out = (float*)d_out;

    k_R<<<FULLN, 256>>>();
    k_gemm_pk<<<dim3(8, 24, 12), 256>>>(Wq_a, Wq_b);

    // weight conversion for the tensor-core FF pair (dst selected in device code)
    dim3 cb(32, 8);
    k_convw<<<dim3(64, 16, 12), cb>>>(W1_a, W1_b, 512, 2048, 1);
    k_convw<<<dim3(16, 64, 12), cb>>>(W2_a, W2_b, 2048, 512, 2);

    for (int s = 0; s < NSEGS; ++s) {
        int buf = s & 1, prev = buf ^ 1;
        if (s > 0) k_shift<<<dim3(512, 12, 2), 256>>>(prev, buf);
        k_embed<<<dim3(512, 2), 128>>>(src, emb, s);
        int vstart = 1024 - (s < 2 ? s : 2) * 512;
        for (int j = 0; j < NLAY; ++j) {
            k_gemm_qkv   <<<dim3(24, 8, 2), 256>>>(Wq_a, Wq_b, uv_a, uv_b, j, buf);
            k_gemm_scores<<<dim3(24, 8, 2), 256>>>(j, buf);
            k_softmax    <<<dim3(512, 2),   256>>>(vstart);
            k_gemm_av    <<<dim3(8, 8, 6),  256>>>(j, buf);        // split-K x3
            k_gemm_wo    <<<dim3(8, 8, 4),  256>>>(Wo_a, Wo_b, j); // split-K x2, A = sum(partials)
            k_ln         <<<dim3(512, 2),   256>>>(ln_a, ln_b, j, 0);
            k_tc         <<<dim3(32, 4, 2), 256>>>(2, j);
            k_tc         <<<dim3(8, 4, 8),  256>>>(3, j);          // split-K x4
            if (j < NLAY - 1) k_ln<<<dim3(512, 2), 256>>>(ln_a, ln_b, j, 1);
            else              k_ln_final<<<dim3(512, 2), 256>>>(ln_a, ln_b, j, s, out);
        }
    }
}

// round 17
// speedup vs baseline: 1.0563x; 1.0516x over previous
#include <cuda_runtime.h>
#include <cuda_bf16.h>
#include <mma.h>
#include <math.h>
#include <stdint.h>

#define SEGN 512
#define NLAY 6
#define NSEGS 8
#define FFD 2048
#define FULLN 1536

typedef unsigned long long u64;
using namespace nvcuda;

// ---------------- packed fp32 math (Blackwell FFMA2, PTX-only) ----------------
__device__ __forceinline__ u64 ffma2(u64 a, u64 b, u64 c) {
    u64 d;
    asm("fma.rn.f32x2 %0, %1, %2, %3;" : "=l"(d) : "l"(a), "l"(b), "l"(c));
    return d;
}
__device__ __forceinline__ u64 pack2(float x, float y) {
    u64 d;
    asm("mov.b64 %0, {%1, %2};" : "=l"(d)
        : "r"(__float_as_uint(x)), "r"(__float_as_uint(y)));
    return d;
}
__device__ __forceinline__ float2 unpk(u64 a) {
    unsigned lo, hi;
    asm("mov.b64 {%0, %1}, %2;" : "=r"(lo), "=r"(hi) : "l"(a));
    return make_float2(__uint_as_float(lo), __uint_as_float(hi));
}

// ---------------- fp32 scratch ----------------
__device__ float g_R[FULLN * 512];
__device__ float g_state[2][SEGN * 512];
__device__ float g_Ap[2][SEGN * 1024];
__device__ float g_kbuf[2][NLAY][2][FULLN * 1024];   // ping-pong [k | pk]
__device__ float g_vbuf[2][NLAY][2][FULLN * 512];    // ping-pong v
__device__ float g_scores[2][SEGN * FULLN];
__device__ float g_h[2][SEGN * 512];
__device__ float g_ffpart[2][4][SEGN * 512];         // split-K partials (av / w2)
__device__ float g_wopart[2][2][SEGN * 512];         // split-K partials (wo)

// ---------------- bf16 split scratch (tensor-core path: W1/W2 only) ----------------
__device__ __nv_bfloat16 g_w1_hi[2][6 * 2048 * 512];   // [j][2048 n][512 k]
__device__ __nv_bfloat16 g_w1_lo[2][6 * 2048 * 512];
__device__ __nv_bfloat16 g_w2_hi[2][6 * 512 * 2048];   // [j][512 n][2048 k]
__device__ __nv_bfloat16 g_w2_lo[2][6 * 512 * 2048];
__device__ __nv_bfloat16 g_hhi[2][SEGN * 512],   g_hlo[2][SEGN * 512];
__device__ __nv_bfloat16 g_midhi[2][SEGN * FFD], g_midlo[2][SEGN * FFD];

__device__ __forceinline__ void split1(float x, __nv_bfloat16* hi, __nv_bfloat16* lo, size_t i) {
    __nv_bfloat16 h = __float2bfloat16_rn(x);
    hi[i] = h;
    lo[i] = __float2bfloat16_rn(x - __bfloat162float(h));
}

// ---------------- R4 FFMA2 GEMM core (BK16, reg prefetch) ----------------
#define GEMM_DECL                                                              \
    __shared__ float As[16][68];                                               \
    __shared__ float Bs[16][68];                                               \
    u64 acc[2][4] = {{0ull,0ull,0ull,0ull},{0ull,0ull,0ull,0ull}};             \
    const int t  = threadIdx.x;                                                \
    const int tx = t & 15, ty = t >> 4;                                        \
    const int ar = t >> 2, ac = (t & 3) << 2;                                  \
    const int br = t >> 4, bc = (t & 15) << 2;                                 \
    const int row0 = blockIdx.y << 6, col0 = blockIdx.x << 6;                  \
    (void)br; (void)bc; (void)row0; (void)col0;

#define INNER16                                                                \
    _Pragma("unroll")                                                          \
    for (int kk = 0; kk < 16; ++kk) {                                          \
        float4 a4 = *(const float4*)&As[kk][ty << 2];                          \
        float4 b4 = *(const float4*)&Bs[kk][tx << 2];                          \
        u64 a01 = pack2(a4.x, a4.y);                                           \
        u64 a23 = pack2(a4.z, a4.w);                                           \
        u64 bb;                                                                \
        bb = pack2(b4.x, b4.x);                                                \
        acc[0][0] = ffma2(a01, bb, acc[0][0]);                                 \
        acc[1][0] = ffma2(a23, bb, acc[1][0]);                                 \
        bb = pack2(b4.y, b4.y);                                                \
        acc[0][1] = ffma2(a01, bb, acc[0][1]);                                 \
        acc[1][1] = ffma2(a23, bb, acc[1][1]);                                 \
        bb = pack2(b4.z, b4.z);                                                \
        acc[0][2] = ffma2(a01, bb, acc[0][2]);                                 \
        acc[1][2] = ffma2(a23, bb, acc[1][2]);                                 \
        bb = pack2(b4.w, b4.w);                                                \
        acc[0][3] = ffma2(a01, bb, acc[0][3]);                                 \
        acc[1][3] = ffma2(a23, bb, acc[1][3]);                                 \
    }

#define GEMM_NN(Aptr, lda, Bptr, ldb, Ktot) {                                  \
    float4 pa = *(const float4*)((Aptr) + (size_t)ar * (lda) + ac);            \
    float4 pb = *(const float4*)((Bptr) + (size_t)br * (ldb) + bc);            \
    for (int kt = 0; kt < (Ktot); kt += 16) {                                  \
        As[ac+0][ar] = pa.x; As[ac+1][ar] = pa.y;                              \
        As[ac+2][ar] = pa.z; As[ac+3][ar] = pa.w;                              \
        *(float4*)&Bs[br][bc] = pb;                                            \
        __syncthreads();                                                       \
        if (kt + 16 < (Ktot)) {                                                \
            pa = *(const float4*)((Aptr) + (size_t)ar * (lda) + kt + 16 + ac); \
            pb = *(const float4*)((Bptr) + (size_t)(kt + 16 + br) * (ldb) + bc); \
        }                                                                      \
        INNER16                                                                \
        __syncthreads();                                                       \
    } }

// A staged as fixed-order sum of up to three partial buffers (order (p0+p1)+p2)
#define LD3(off) \
    [&]{ float4 v0 = *(const float4*)((A0) + (off));                           \
         if (nch > 1) { float4 v1 = *(const float4*)((A1) + (off));            \
             v0.x += v1.x; v0.y += v1.y; v0.z += v1.z; v0.w += v1.w; }         \
         if (nch > 2) { float4 v2 = *(const float4*)((A2) + (off));            \
             v0.x += v2.x; v0.y += v2.y; v0.z += v2.z; v0.w += v2.w; }         \
         return v0; }()

#define GEMM_NN3(lda, Bptr, ldb, Ktot) {                                       \
    float4 pa = LD3((size_t)ar * (lda) + ac);                                  \
    float4 pb = *(const float4*)((Bptr) + (size_t)br * (ldb) + bc);            \
    for (int kt = 0; kt < (Ktot); kt += 16) {                                  \
        As[ac+0][ar] = pa.x; As[ac+1][ar] = pa.y;                              \
        As[ac+2][ar] = pa.z; As[ac+3][ar] = pa.w;                              \
        *(float4*)&Bs[br][bc] = pb;                                            \
        __syncthreads();                                                       \
        if (kt + 16 < (Ktot)) {                                                \
            pa = LD3((size_t)ar * (lda) + kt + 16 + ac);                       \
            pb = *(const float4*)((Bptr) + (size_t)(kt + 16 + br) * (ldb) + bc); \
        }                                                                      \
        INNER16                                                                \
        __syncthreads();                                                       \
    } }

#define GEMM_NT(Aptr, lda, Bptr, ldb, Ktot) {                                  \
    float4 pa = *(const float4*)((Aptr) + (size_t)ar * (lda) + ac);            \
    float4 pb = *(const float4*)((Bptr) + (size_t)ar * (ldb) + ac);            \
    for (int kt = 0; kt < (Ktot); kt += 16) {                                  \
        As[ac+0][ar] = pa.x; As[ac+1][ar] = pa.y;                              \
        As[ac+2][ar] = pa.z; As[ac+3][ar] = pa.w;                              \
        Bs[ac+0][ar] = pb.x; Bs[ac+1][ar] = pb.y;                              \
        Bs[ac+2][ar] = pb.z; Bs[ac+3][ar] = pb.w;                              \
        __syncthreads();                                                       \
        if (kt + 16 < (Ktot)) {                                                \
            pa = *(const float4*)((Aptr) + (size_t)ar * (lda) + kt + 16 + ac); \
            pb = *(const float4*)((Bptr) + (size_t)ar * (ldb) + kt + 16 + ac); \
        }                                                                      \
        INNER16                                                                \
        __syncthreads();                                                       \
    } }

#define GEMM_EPI                                                               \
    float rowv[4][4];                                                          \
    _Pragma("unroll")                                                          \
    for (int c = 0; c < 4; ++c) {                                              \
        float2 v0 = unpk(acc[0][c]);                                           \
        float2 v1 = unpk(acc[1][c]);                                           \
        rowv[0][c] = v0.x; rowv[1][c] = v0.y;                                  \
        rowv[2][c] = v1.x; rowv[3][c] = v1.y;                                  \
    }

// weight convert + transpose + split: src [K,N] fp32 -> dst [N,K] bf16 hi/lo.
// which: 1=w1, 2=w2. dst selected IN DEVICE CODE (ATS host-shadow pitfall).
__global__ void k_convw(const float* srcA, const float* srcB, int K, int N, int which) {
    int z = blockIdx.z;
    int e = z / NLAY, j = z % NLAY;
    const float* src = (e ? srcB : srcA) + (size_t)j * K * N;
    size_t doff = (size_t)j * K * N;
    __nv_bfloat16* hi = (which == 1) ? g_w1_hi[e] + doff : g_w2_hi[e] + doff;
    __nv_bfloat16* lo = (which == 1) ? g_w1_lo[e] + doff : g_w2_lo[e] + doff;

    __shared__ float tile[32][33];
    int n0 = blockIdx.x * 32, k0 = blockIdx.y * 32;
    int tx = threadIdx.x, ty = threadIdx.y;
#pragma unroll
    for (int r = 0; r < 32; r += 8)
        tile[ty + r][tx] = src[(size_t)(k0 + ty + r) * N + n0 + tx];
    __syncthreads();
#pragma unroll
    for (int r = 0; r < 32; r += 8) {
        float x = tile[tx][ty + r];
        size_t o = (size_t)(n0 + ty + r) * K + k0 + tx;
        split1(x, hi, lo, o);
    }
}

// ---------- WMMA GEMM (validated): C[128x64] = act @ Wt^T, bf16x3 split ----------
// mode 2: w1 (A = h split, relu -> mid split), z = e
// mode 3: w2 split-K: z = kc*2 + e, chunk K=512, partial -> g_ffpart[e][kc]
__global__ void __launch_bounds__(256) k_tc(int mode, int j) {
    __shared__ __align__(16) char smem_raw[36864];
    __nv_bfloat16 (*sAh)[40] = (__nv_bfloat16(*)[40])(smem_raw);
    __nv_bfloat16 (*sAl)[40] = (__nv_bfloat16(*)[40])(smem_raw + 10240);
    __nv_bfloat16 (*sBh)[40] = (__nv_bfloat16(*)[40])(smem_raw + 20480);
    __nv_bfloat16 (*sBl)[40] = (__nv_bfloat16(*)[40])(smem_raw + 25600);

    const int t = threadIdx.x;
    const int e = blockIdx.z & 1;
    const int kc = blockIdx.z >> 1;
    const int nb = blockIdx.x;
    const int row0 = blockIdx.y << 7;
    const int lane = t & 31, w = t >> 5;
    const int wm = w & 3, wn = w >> 2;

    const __nv_bfloat16 *Ah, *Al, *Bh, *Bl;
    int Kld;
    if (mode == 2) {
        Ah = g_hhi[e]; Al = g_hlo[e];
        size_t woff = ((size_t)j * 2048 + nb * 64) * 512;
        Bh = g_w1_hi[e] + woff; Bl = g_w1_lo[e] + woff; Kld = 512;
    } else {
        Ah = g_midhi[e]; Al = g_midlo[e];
        size_t woff = ((size_t)j * 512 + nb * 64) * 2048;
        Bh = g_w2_hi[e] + woff; Bl = g_w2_lo[e] + woff; Kld = 2048;
    }
    const int k0 = kc * 512;
    Ah += (size_t)row0 * Kld + k0;
    Al += (size_t)row0 * Kld + k0;
    Bh += k0;
    Bl += k0;

    wmma::fragment<wmma::accumulator, 16, 16, 16, float> facc[2][2];
#pragma unroll
    for (int i = 0; i < 2; ++i)
#pragma unroll
        for (int jj = 0; jj < 2; ++jj)
            wmma::fill_fragment(facc[i][jj], 0.0f);

    for (int kt = 0; kt < 512; kt += 32) {
#pragma unroll
        for (int i = 0; i < 2; ++i) {
            int idx = t + i * 256;
            int r = idx >> 2, s = idx & 3;
            *(uint4*)&sAh[r][s * 8] = *(const uint4*)(Ah + (size_t)r * Kld + kt + s * 8);
            *(uint4*)&sAl[r][s * 8] = *(const uint4*)(Al + (size_t)r * Kld + kt + s * 8);
        }
        {
            int r = t >> 2, s = t & 3;
            *(uint4*)&sBh[r][s * 8] = *(const uint4*)(Bh + (size_t)r * Kld + kt + s * 8);
            *(uint4*)&sBl[r][s * 8] = *(const uint4*)(Bl + (size_t)r * Kld + kt + s * 8);
        }
        __syncthreads();

#pragma unroll
        for (int kk = 0; kk < 32; kk += 16) {
            wmma::fragment<wmma::matrix_a, 16, 16, 16, __nv_bfloat16, wmma::row_major> fAh, fAl;
            wmma::fragment<wmma::matrix_b, 16, 16, 16, __nv_bfloat16, wmma::col_major> fBh, fBl;
#pragma unroll
            for (int i = 0; i < 2; ++i) {
                wmma::load_matrix_sync(fAh, &sAh[(wm << 5) + (i << 4)][kk], 40);
                wmma::load_matrix_sync(fAl, &sAl[(wm << 5) + (i << 4)][kk], 40);
#pragma unroll
                for (int jj = 0; jj < 2; ++jj) {
                    wmma::load_matrix_sync(fBh, &sBh[(wn << 5) + (jj << 4)][kk], 40);
                    wmma::load_matrix_sync(fBl, &sBl[(wn << 5) + (jj << 4)][kk], 40);
                    wmma::mma_sync(facc[i][jj], fAh, fBh, facc[i][jj]);
                    wmma::mma_sync(facc[i][jj], fAh, fBl, facc[i][jj]);
                    wmma::mma_sync(facc[i][jj], fAl, fBh, facc[i][jj]);
                }
            }
        }
        __syncthreads();
    }

    float* sCw = (float*)smem_raw + w * (32 * 36);
#pragma unroll
    for (int i = 0; i < 2; ++i)
#pragma unroll
        for (int jj = 0; jj < 2; ++jj)
            wmma::store_matrix_sync(sCw + (i * 16) * 36 + jj * 16, facc[i][jj], 36,
                                    wmma::mem_row_major);
    __syncwarp();

    const int m = row0 + (wm << 5) + lane;
    if (mode == 2) {
        size_t o = (size_t)m * FFD + (nb << 6) + (wn << 5);
#pragma unroll
        for (int c = 0; c < 32; ++c) {
            float v = sCw[lane * 36 + c];
            split1(fmaxf(v, 0.f), g_midhi[e], g_midlo[e], o + c);
        }
    } else {
        float* P = g_ffpart[e][kc] + (size_t)m * 512 + (nb << 6) + (wn << 5);
#pragma unroll
        for (int c = 0; c < 32; ++c) P[c] = sCw[lane * 36 + c];
    }
}

// ---------------- init: sinusoid table (flipped) ----------------
__global__ void k_R() {
    int i = blockIdx.x;
    int pos = FULLN - 1 - i;
    for (int dd = threadIdx.x; dd < 512; dd += 256) {
        int i2 = dd >> 1;
        float denom = powf(10000.0f, (float)(2 * i2) / 512.0f);
        double a = (double)((float)pos / denom);
        g_R[(size_t)i * 512 + dd] = (dd & 1) ? (float)cos(a) : (float)sin(a);
    }
}

// pk[e][j] = R @ Wr_j  -> both ping-pong kbuf buffers, cols 512..1024
__global__ void __launch_bounds__(256) k_gemm_pk(const float* Wa, const float* Wb) {
    int z = blockIdx.z;
    int e = z / NLAY, layer = z % NLAY;
    GEMM_DECL
    const float* A = g_R + (size_t)row0 * 512;
    const float* B = (e ? Wb : Wa) + ((size_t)layer * 4 + 3) * 262144 + col0;
    GEMM_NN(A, 512, B, 512, 512)
    GEMM_EPI
#pragma unroll
    for (int i = 0; i < 4; ++i) {
        float4 o = make_float4(rowv[i][0], rowv[i][1], rowv[i][2], rowv[i][3]);
        size_t off = (size_t)(row0 + (ty << 2) + i) * 1024 + 512 + col0 + (tx << 2);
        *(float4*)&g_kbuf[e][layer][0][off] = o;
        *(float4*)&g_kbuf[e][layer][1][off] = o;
    }
}

// state = emb[token]
__global__ void k_embed(const int* src, const float* emb, int s) {
    int e = blockIdx.y, m = blockIdx.x;
    int gpos = s * SEGN + m;
    int tok = e ? src[4095 - gpos] : src[gpos];
    const float4* sr = (const float4*)(emb + (size_t)tok * 512);
    float4* dst = (float4*)(g_state[e] + (size_t)m * 512);
    dst[threadIdx.x] = sr[threadIdx.x];
}

// shift cached k/v: buf[prev] rows 512..1536 -> buf[cur] rows 0..1024
__global__ void k_shift(int prev, int cur) {
    int e = blockIdx.z;
    int l = blockIdx.y >> 1, w = blockIdx.y & 1;
    int i = blockIdx.x * 256 + threadIdx.x;
    int row = i >> 7;
    int c4 = (i & 127) << 2;
    if (w == 0) {
        float4 v = *(const float4*)&g_kbuf[e][l][prev][(size_t)(row + 512) * 1024 + c4];
        *(float4*)&g_kbuf[e][l][cur][(size_t)row * 1024 + c4] = v;
    } else {
        float4 v = *(const float4*)&g_vbuf[e][l][prev][(size_t)(row + 512) * 512 + c4];
        *(float4*)&g_vbuf[e][l][cur][(size_t)row * 512 + c4] = v;
    }
}

// merged q/k/v for CURRENT segment (R4 FFMA2, known good)
__global__ void __launch_bounds__(256) k_gemm_qkv(const float* Wa, const float* Wb,
                                                  const float* uva, const float* uvb,
                                                  int j, int buf) {
    int e = blockIdx.z;
    GEMM_DECL
    const int mat = col0 >> 9, n0 = col0 & 511;
    const float* A = g_state[e] + (size_t)row0 * 512;
    const float* B = (e ? Wb : Wa) + ((size_t)j * 4 + mat) * 262144 + n0;
    GEMM_NN(A, 512, B, 512, 512)
    GEMM_EPI
    if (mat == 0) {
        const float* uv = e ? uvb : uva;
        float* Ap = g_Ap[e];
#pragma unroll
        for (int i = 0; i < 4; ++i) {
            int m = row0 + (ty << 2) + i;
            int n = n0 + (tx << 2);
            float4 o1 = make_float4(rowv[i][0] + uv[n],     rowv[i][1] + uv[n + 1],
                                    rowv[i][2] + uv[n + 2], rowv[i][3] + uv[n + 3]);
            float4 o2 = make_float4(rowv[i][0] + uv[512 + n],     rowv[i][1] + uv[512 + n + 1],
                                    rowv[i][2] + uv[512 + n + 2], rowv[i][3] + uv[512 + n + 3]);
            *(float4*)&Ap[(size_t)m * 1024 + n] = o1;
            *(float4*)&Ap[(size_t)m * 1024 + 512 + n] = o2;
        }
    } else if (mat == 1) {
        float* C = g_kbuf[e][j][buf];
#pragma unroll
        for (int i = 0; i < 4; ++i) {
            float4 o = make_float4(rowv[i][0], rowv[i][1], rowv[i][2], rowv[i][3]);
            *(float4*)&C[(size_t)(1024 + row0 + (ty << 2) + i) * 1024 + n0 + (tx << 2)] = o;
        }
    } else {
        float* C = g_vbuf[e][j][buf];
#pragma unroll
        for (int i = 0; i < 4; ++i) {
            float4 o = make_float4(rowv[i][0], rowv[i][1], rowv[i][2], rowv[i][3]);
            *(float4*)&C[(size_t)(1024 + row0 + (ty << 2) + i) * 512 + n0 + (tx << 2)] = o;
        }
    }
}

// scores = Ap @ kbuf[buf]^T * scale, only live columns [vstart, 1536)
__global__ void __launch_bounds__(256) k_gemm_scores(int layer, int buf, int vstart) {
    int e = blockIdx.z;
    GEMM_DECL
    const int c0 = vstart + col0;         // live-window column origin
    const float* A = g_Ap[e] + (size_t)row0 * 1024;
    const float* B = g_kbuf[e][layer][buf] + (size_t)c0 * 1024;
    GEMM_NT(A, 1024, B, 1024, 1024)
    GEMM_EPI
    const float scale = 0.04419417382415922f;
    float* C = g_scores[e];
#pragma unroll
    for (int i = 0; i < 4; ++i) {
        float4 o = make_float4(rowv[i][0] * scale, rowv[i][1] * scale,
                               rowv[i][2] * scale, rowv[i][3] * scale);
        *(float4*)&C[(size_t)(row0 + (ty << 2) + i) * FULLN + c0 + (tx << 2)] = o;
    }
}

// row softmax over [vstart, 1536); zeros below
__global__ void k_softmax(int vstart) {
    int e = blockIdx.y, tid = threadIdx.x;
    float* s = g_scores[e] + (size_t)blockIdx.x * FULLN;
    __shared__ float red[256];
    float mx = -3.0e38f;
    for (int c = vstart + tid; c < FULLN; c += 256) mx = fmaxf(mx, s[c]);
    red[tid] = mx; __syncthreads();
    for (int o = 128; o; o >>= 1) { if (tid < o) red[tid] = fmaxf(red[tid], red[tid + o]); __syncthreads(); }
    mx = red[0]; __syncthreads();
    float sum = 0.f;
    for (int c = vstart + tid; c < FULLN; c += 256) { float v = expf(s[c] - mx); s[c] = v; sum += v; }
    red[tid] = sum; __syncthreads();
    for (int o = 128; o; o >>= 1) { if (tid < o) red[tid] += red[tid + o]; __syncthreads(); }
    float inv = 1.f / red[0];
    for (int c = tid; c < vstart; c += 256) s[c] = 0.f;
    for (int c = vstart + tid; c < FULLN; c += 256) s[c] *= inv;
}

// av split-K over LIVE chunks only: z = kc*2 + e; chunk = kc0 + kc.
// masked chunks contribute exactly 0 (attn is exact zero there) -> skipping is bit-exact
__global__ void __launch_bounds__(256) k_gemm_av(int layer, int buf, int kc0) {
    int e = blockIdx.z & 1, kc = blockIdx.z >> 1;
    int chunk = kc0 + kc;
    GEMM_DECL
    const float* A = g_scores[e] + (size_t)row0 * FULLN + chunk * 512;
    const float* B = g_vbuf[e][layer][buf] + (size_t)(chunk * 512) * 512 + col0;
    GEMM_NN(A, FULLN, B, 512, 512)
    GEMM_EPI
    float* P = g_ffpart[e][kc];
#pragma unroll
    for (int i = 0; i < 4; ++i) {
        float4 o = make_float4(rowv[i][0], rowv[i][1], rowv[i][2], rowv[i][3]);
        *(float4*)&P[(size_t)(row0 + (ty << 2) + i) * 512 + col0 + (tx << 2)] = o;
    }
}

// wo split-K x2: A = prefix-sum of nch live av partials (same order as before);
// partials -> g_wopart[e][kc]
__global__ void __launch_bounds__(256) k_gemm_wo(const float* Wa, const float* Wb,
                                                 int layer, int nch) {
    int e = blockIdx.z & 1, kc = blockIdx.z >> 1;
    GEMM_DECL
    const float* A0 = g_ffpart[e][0] + (size_t)row0 * 512 + kc * 256;
    const float* A1 = g_ffpart[e][1] + (size_t)row0 * 512 + kc * 256;
    const float* A2 = g_ffpart[e][2] + (size_t)row0 * 512 + kc * 256;
    const float* B = (e ? Wb : Wa) + (size_t)layer * 262144 + (size_t)(kc * 256) * 512 + col0;
    GEMM_NN3(512, B, 512, 256)
    GEMM_EPI
    float* P = g_wopart[e][kc];
#pragma unroll
    for (int i = 0; i < 4; ++i) {
        float4 o = make_float4(rowv[i][0], rowv[i][1], rowv[i][2], rowv[i][3]);
        *(float4*)&P[(size_t)(row0 + (ty << 2) + i) * 512 + col0 + (tx << 2)] = o;
    }
}

// layernorm (reduction folded in).
// mode 0: x = state + wop0 + wop1 -> g_h (+ h split for w1)
// mode 1: x = h + (((p0+p1)+p2)+p3) (w2 partials) -> g_state
__global__ void k_ln(const float* lnA, const float* lnB, int layer, int mode) {
    int e = blockIdx.y, row = blockIdx.x, tid = threadIdx.x;
    size_t o = (size_t)row * 512;
    float x0, x1;
    if (mode == 0) {
        x0 = g_state[e][o + tid]       + g_wopart[e][0][o + tid]       + g_wopart[e][1][o + tid];
        x1 = g_state[e][o + tid + 256] + g_wopart[e][0][o + tid + 256] + g_wopart[e][1][o + tid + 256];
    } else {
        x0 = g_h[e][o + tid] + (((g_ffpart[e][0][o + tid] + g_ffpart[e][1][o + tid])
              + g_ffpart[e][2][o + tid]) + g_ffpart[e][3][o + tid]);
        x1 = g_h[e][o + tid + 256] + (((g_ffpart[e][0][o + tid + 256] + g_ffpart[e][1][o + tid + 256])
              + g_ffpart[e][2][o + tid + 256]) + g_ffpart[e][3][o + tid + 256]);
    }
    const float* ln = (e ? lnB : lnA) + ((size_t)layer * 4 + 2 * mode) * 512;
    __shared__ float red[256];
    red[tid] = x0 + x1; __syncthreads();
    for (int s = 128; s; s >>= 1) { if (tid < s) red[tid] += red[tid + s]; __syncthreads(); }
    float mu = red[0] * (1.f / 512.f); __syncthreads();
    float d0 = x0 - mu, d1 = x1 - mu;
    red[tid] = d0 * d0 + d1 * d1; __syncthreads();
    for (int s = 128; s; s >>= 1) { if (tid < s) red[tid] += red[tid + s]; __syncthreads(); }
    float r = rsqrtf(red[0] * (1.f / 512.f) + 1e-5f);
    float o0 = d0 * r * ln[tid] + ln[512 + tid];
    float o1 = d1 * r * ln[tid + 256] + ln[512 + tid + 256];
    float* out = mode ? g_state[e] : g_h[e];
    out[o + tid] = o0;
    out[o + tid + 256] = o1;
    if (mode == 0) {
        split1(o0, g_hhi[e], g_hlo[e], o + tid);
        split1(o1, g_hhi[e], g_hlo[e], o + tid + 256);
    }
}

// last-layer LN2 (mode-1 input) -> output with fwd/rev mapping
__global__ void k_ln_final(const float* lnA, const float* lnB, int layer, int s, float* out) {
    int e = blockIdx.y, row = blockIdx.x, tid = threadIdx.x;
    size_t o = (size_t)row * 512;
    float x0 = g_h[e][o + tid] + (((g_ffpart[e][0][o + tid] + g_ffpart[e][1][o + tid])
              + g_ffpart[e][2][o + tid]) + g_ffpart[e][3][o + tid]);
    float x1 = g_h[e][o + tid + 256] + (((g_ffpart[e][0][o + tid + 256] + g_ffpart[e][1][o + tid + 256])
              + g_ffpart[e][2][o + tid + 256]) + g_ffpart[e][3][o + tid + 256]);
    const float* ln = (e ? lnB : lnA) + ((size_t)layer * 4 + 2) * 512;
    __shared__ float red[256];
    red[tid] = x0 + x1; __syncthreads();
    for (int sft = 128; sft; sft >>= 1) { if (tid < sft) red[tid] += red[tid + sft]; __syncthreads(); }
    float mu = red[0] * (1.f / 512.f); __syncthreads();
    float d0 = x0 - mu, d1 = x1 - mu;
    red[tid] = d0 * d0 + d1 * d1; __syncthreads();
    for (int sft = 128; sft; sft >>= 1) { if (tid < sft) red[tid] += red[tid + sft]; __syncthreads(); }
    float r = rsqrtf(red[0] * (1.f / 512.f) + 1e-5f);
    int g = s * SEGN + row;
    float* dst = e ? (out + (size_t)(4095 - g) * 1024 + 512) : (out + (size_t)g * 1024);
    dst[tid]       = d0 * r * ln[tid]       + ln[512 + tid];
    dst[tid + 256] = d1 * r * ln[tid + 256] + ln[512 + tid + 256];
}

// ---------------- host orchestration (graph-capturable: launches only) ----------------
extern "C" void kernel_launch(void* const* d_in, const int* in_sizes, int n_in,
                              void* d_out, int out_size) {
    const int*   src  = (const int*)d_in[0];
    const float* emb  = (const float*)d_in[2];
    const float* Wq_a = (const float*)d_in[3];
    const float* Wo_a = (const float*)d_in[4];
    const float* W1_a = (const float*)d_in[5];
    const float* W2_a = (const float*)d_in[6];
    const float* ln_a = (const float*)d_in[7];
    const float* uv_a = (const float*)d_in[8];
    const float* Wq_b = (const float*)d_in[9];
    const float* Wo_b = (const float*)d_in[10];
    const float* W1_b = (const float*)d_in[11];
    const float* W2_b = (const float*)d_in[12];
    const float* ln_b = (const float*)d_in[13];
    const float* uv_b = (const float*)d_in[14];
    float* out = (float*)d_out;

    k_R<<<FULLN, 256>>>();
    k_gemm_pk<<<dim3(8, 24, 12), 256>>>(Wq_a, Wq_b);

    // weight conversion for the tensor-core FF pair (dst selected in device code)
    dim3 cb(32, 8);
    k_convw<<<dim3(64, 16, 12), cb>>>(W1_a, W1_b, 512, 2048, 1);
    k_convw<<<dim3(16, 64, 12), cb>>>(W2_a, W2_b, 2048, 512, 2);

    for (int s = 0; s < NSEGS; ++s) {
        int buf = s & 1, prev = buf ^ 1;
        if (s > 0) k_shift<<<dim3(512, 12, 2), 256>>>(prev, buf);
        k_embed<<<dim3(512, 2), 128>>>(src, emb, s);
        int vstart = 1024 - (s < 2 ? s : 2) * 512;
        int nlive = (FULLN - vstart) >> 6;       // live 64-col blocks: 8 / 16 / 24
        int kc0 = vstart >> 9;                   // first live 512-chunk: 2 / 1 / 0
        int nch = 3 - kc0;                       // live chunks: 1 / 2 / 3
        for (int j = 0; j < NLAY; ++j) {
            k_gemm_qkv   <<<dim3(24, 8, 2),       256>>>(Wq_a, Wq_b, uv_a, uv_b, j, buf);
            k_gemm_scores<<<dim3(nlive, 8, 2),    256>>>(j, buf, vstart);
            k_softmax    <<<dim3(512, 2),         256>>>(vstart);
            k_gemm_av    <<<dim3(8, 8, 2 * nch),  256>>>(j, buf, kc0);
            k_gemm_wo    <<<dim3(8, 8, 4),        256>>>(Wo_a, Wo_b, j, nch);
            k_ln         <<<dim3(512, 2),         256>>>(ln_a, ln_b, j, 0);
            k_tc         <<<dim3(32, 4, 2),       256>>>(2, j);
            k_tc         <<<dim3(8, 4, 8),        256>>>(3, j);
            if (j < NLAY - 1) k_ln<<<dim3(512, 2), 256>>>(ln_a, ln_b, j, 1);
            else              k_ln_final<<<dim3(512, 2), 256>>>(ln_a, ln_b, j, s, out);
        }
    }
}